// round 6
// baseline (speedup 1.0000x reference)
#include <cuda_runtime.h>
#include <cstdint>

// Problem constants
#define TT 512
#define BB 128
#define DD 256
#define HH 256

// ---- packed fp32x2 helpers (Blackwell) ----
#define FMA_F32X2(d, a, b, c) \
    asm("fma.rn.f32x2 %0, %1, %2, %3;" : "=l"(d) : "l"(a), "l"(b), "l"(c))
#define PACK_F32X2(out, lo, hi) \
    asm("mov.b64 %0, {%1, %2};" : "=l"(out) : "f"(lo), "f"(hi))
#define UNPACK_F32X2(lo, hi, in) \
    asm("mov.b64 {%0, %1}, %2;" : "=f"(lo), "=f"(hi) : "l"(in))

union F4U2 { float4 f4; uint64_t u2[2]; };

// =====================================================================
// Phase 1:  pre[t,b,j] = sum_d X[t,b,d] * Wi[j,d] + bh[j]
// GEMM  M = 65536, N = 256, K = 256 -> d_out. f32x2-packed microtile.
// (unchanged: measured ~145-190 us, ~82% of f32x2 issue floor)
// =====================================================================
#define P1_BM 64
#define P1_BK 32
#define P1_BMP 66   // EVEN padded stride -> 8B-aligned LDS.64 a-pairs
#define P1_BNP 257  // padded stride for Bs

__global__ __launch_bounds__(256, 2)
void pre_gemm(const float* __restrict__ X, const float* __restrict__ Wi,
              const float* __restrict__ bh, float* __restrict__ out)
{
    __shared__ __align__(16) float As[P1_BK * P1_BMP];   // As[k][m]
    __shared__ __align__(16) float Bs[P1_BK * P1_BNP];   // Bs[k][n]

    const int tid = threadIdx.x;
    const int tx = tid & 31;
    const int ty = tid >> 5;
    const int row0 = blockIdx.x * P1_BM;

    uint64_t acc2[4][8];
#pragma unroll
    for (int r = 0; r < 4; r++)
#pragma unroll
        for (int c = 0; c < 8; c++) acc2[r][c] = 0ull;

    for (int k0 = 0; k0 < DD; k0 += P1_BK) {
#pragma unroll
        for (int i = 0; i < 2; i++) {
            int lin = i * 256 + tid;
            int m  = lin >> 3;
            int kq = lin & 7;
            float4 v = *(const float4*)(X + (row0 + m) * DD + k0 + kq * 4);
            As[(kq * 4 + 0) * P1_BMP + m] = v.x;
            As[(kq * 4 + 1) * P1_BMP + m] = v.y;
            As[(kq * 4 + 2) * P1_BMP + m] = v.z;
            As[(kq * 4 + 3) * P1_BMP + m] = v.w;
        }
#pragma unroll
        for (int i = 0; i < 8; i++) {
            int lin = i * 256 + tid;
            int n  = lin >> 3;
            int kq = lin & 7;
            float4 v = *(const float4*)(Wi + n * DD + k0 + kq * 4);
            Bs[(kq * 4 + 0) * P1_BNP + n] = v.x;
            Bs[(kq * 4 + 1) * P1_BNP + n] = v.y;
            Bs[(kq * 4 + 2) * P1_BNP + n] = v.z;
            Bs[(kq * 4 + 3) * P1_BNP + n] = v.w;
        }
        __syncthreads();

#pragma unroll 8
        for (int k = 0; k < P1_BK; k++) {
            const uint64_t* ap = (const uint64_t*)(As + k * P1_BMP + ty * 8);
            uint64_t a2[4];
            a2[0] = ap[0]; a2[1] = ap[1]; a2[2] = ap[2]; a2[3] = ap[3];
#pragma unroll
            for (int c = 0; c < 8; c++) {
                float bv = Bs[k * P1_BNP + c * 32 + tx];
                uint64_t bb;
                PACK_F32X2(bb, bv, bv);
#pragma unroll
                for (int r = 0; r < 4; r++)
                    FMA_F32X2(acc2[r][c], a2[r], bb, acc2[r][c]);
            }
        }
        __syncthreads();
    }

    float bias[8];
#pragma unroll
    for (int c = 0; c < 8; c++) bias[c] = bh[c * 32 + tx];
#pragma unroll
    for (int r = 0; r < 4; r++) {
        float* orow0 = out + (row0 + ty * 8 + 2 * r + 0) * HH;
        float* orow1 = out + (row0 + ty * 8 + 2 * r + 1) * HH;
#pragma unroll
        for (int c = 0; c < 8; c++) {
            float lo, hi;
            UNPACK_F32X2(lo, hi, acc2[r][c]);
            orow0[c * 32 + tx] = lo + bias[c];
            orow1[c * 32 + tx] = hi + bias[c];
        }
    }
}

// =====================================================================
// Phase 2: sequential recurrence, k-split x2, symmetric tail, f32x2.
// One CTA per batch row b (128 CTAs), 512 threads = 16 warps.
//   tid = half*256 + j;  half owns k range [half*128, half*128+128)
//   Wh[j][kbase+0  .. kbase+95 ]  -> 24 float4 registers per thread
//   Wh[j][kbase+96 .. kbase+127]  -> smem, interleaved for LDS.128
//   h -> smem double buffer, broadcast LDS.128 (uniform addr per warp)
// Tail: both halves exchange partials via part_s, both compute sigmoid;
//       half0 stores out[t], half1 stores h_s[next].
// Dot product uses fma.rn.f32x2: 64 FMA2/thread in 4 chains (bit-exact).
// =====================================================================
#define P2_T    512
#define P2_KREG 96                      // per-thread k-values in registers
#define P2_KSM  32                      // per-thread k-values in smem
#define WHS_FLOATS (8 * 2048)           // 8 c-groups x 512 thr x 4 = 64KB
#define P2_SMEM_FLOATS (WHS_FLOATS + 2 * HH + P2_T)
#define P2_SMEM_BYTES (P2_SMEM_FLOATS * (int)sizeof(float))

__global__ __launch_bounds__(P2_T, 1)
void rnn_seq(const float* __restrict__ Wh, const float* __restrict__ h0,
             float* __restrict__ out)
{
    extern __shared__ __align__(16) float sm[];
    float* Wh_s   = sm;                       // 16384 floats
    float* h_s    = sm + WHS_FLOATS;          // 2 x 256
    float* part_s = sm + WHS_FLOATS + 2 * HH; // 512 (per-half partials)

    const int tid  = threadIdx.x;
    const int j    = tid & 255;
    const int half = tid >> 8;                // 0: k in [0,128), 1: [128,256)
    const int kbase = half * 128;
    const int b = blockIdx.x;

    // ---- register-resident weights: Wh[j][kbase .. kbase+95] ----
    F4U2 wr[P2_KREG / 4];
#pragma unroll
    for (int i = 0; i < P2_KREG / 4; i++)
        wr[i].f4 = *(const float4*)(Wh + j * HH + kbase + i * 4);

    // ---- smem-resident weights (interleaved for conflict-free LDS.128) ----
    for (int idx = tid; idx < P2_T * P2_KSM; idx += P2_T) {
        int k  = idx & 31;
        int tt = idx >> 5;
        int jj = tt & 255;
        int kk = (tt >> 8) * 128 + P2_KREG + k;
        Wh_s[(k >> 2) * 2048 + tt * 4 + (k & 3)] = Wh[jj * HH + kk];
    }
    if (tid < HH) h_s[tid] = h0[b * HH + tid];
    __syncthreads();

    const int base = b * HH + j;
    float pre = 0.0f;
    if (half == 0) pre = out[base];           // pre[0]

    const float4* wsm = (const float4*)(Wh_s) + tid;  // + c*512 per group
    const int other = (half ^ 1) * 256 + j;

    for (int t = 0; t < TT; t++) {
        float pre_next = 0.0f;
        if (half == 0 && t + 1 < TT)
            pre_next = out[(t + 1) * (BB * HH) + base];

        const float* hc = h_s + (t & 1) * HH + kbase;

        // 4 independent packed accumulator chains
        uint64_t s0, s1, s2, s3;
        PACK_F32X2(s0, pre, 0.0f);
        s1 = 0ull; s2 = 0ull; s3 = 0ull;

        // k-offsets 0..95: register weights, h broadcast from smem
#pragma unroll
        for (int c = 0; c < P2_KREG / 4; c += 2) {
            F4U2 ha, hb;
            ha.f4 = *(const float4*)(hc + c * 4);
            hb.f4 = *(const float4*)(hc + c * 4 + 4);
            FMA_F32X2(s0, ha.u2[0], wr[c].u2[0], s0);
            FMA_F32X2(s1, ha.u2[1], wr[c].u2[1], s1);
            FMA_F32X2(s2, hb.u2[0], wr[c + 1].u2[0], s2);
            FMA_F32X2(s3, hb.u2[1], wr[c + 1].u2[1], s3);
        }
        // k-offsets 96..127: smem weights, conflict-free LDS.128
#pragma unroll
        for (int c = 0; c < P2_KSM / 4; c += 2) {
            F4U2 ha, hb, wa, wb;
            ha.f4 = *(const float4*)(hc + P2_KREG + c * 4);
            hb.f4 = *(const float4*)(hc + P2_KREG + c * 4 + 4);
            wa.f4 = wsm[c * 512];
            wb.f4 = wsm[(c + 1) * 512];
            FMA_F32X2(s0, ha.u2[0], wa.u2[0], s0);
            FMA_F32X2(s1, ha.u2[1], wa.u2[1], s1);
            FMA_F32X2(s2, hb.u2[0], wb.u2[0], s2);
            FMA_F32X2(s3, hb.u2[1], wb.u2[1], s3);
        }

        float l0, u0, l1, u1, l2, u2v, l3, u3;
        UNPACK_F32X2(l0, u0, s0);
        UNPACK_F32X2(l1, u1, s1);
        UNPACK_F32X2(l2, u2v, s2);
        UNPACK_F32X2(l3, u3, s3);
        float s = ((l0 + u0) + (l1 + u1)) + ((l2 + u2v) + (l3 + u3));

        part_s[tid] = s;                       // publish own partial
        __syncthreads();

        float z = s + part_s[other];           // symmetric exchange
        float hn = __fdividef(1.0f, 1.0f + __expf(-z));
        if (half)
            h_s[((t + 1) & 1) * HH + j] = hn;  // half1 publishes next h
        else
            out[t * (BB * HH) + base] = hn;    // half0 writes the output
        __syncthreads();
        pre = pre_next;
    }
}

// =====================================================================
// Launch
// Inputs: X [T,B,D], h [B,H], Wi [H,D], Wh [H,H], bh [H], many_to_many.
// =====================================================================
extern "C" void kernel_launch(void* const* d_in, const int* in_sizes, int n_in,
                              void* d_out, int out_size)
{
    const float* X  = (const float*)d_in[0];
    const float* h0 = (const float*)d_in[1];
    const float* Wi = (const float*)d_in[2];
    const float* Wh = (const float*)d_in[3];
    const float* bh = (const float*)d_in[4];
    float* out = (float*)d_out;

    pre_gemm<<<(TT * BB) / P1_BM, 256>>>(X, Wi, bh, out);

    cudaFuncSetAttribute(rnn_seq, cudaFuncAttributeMaxDynamicSharedMemorySize,
                         P2_SMEM_BYTES);
    rnn_seq<<<BB, P2_T, P2_SMEM_BYTES>>>(Wh, h0, out);
}

// round 8
// speedup vs baseline: 1.1502x; 1.1502x over previous
#include <cuda_runtime.h>
#include <cstdint>

// Problem constants
#define TT 512
#define BB 128
#define DD 256
#define HH 256

// ---- packed fp32x2 helpers (pre_gemm ONLY: measured -32% there, and
//      measured +27..30% REGRESSION in the latency-bound recurrence) ----
#define FMA_F32X2(d, a, b, c) \
    asm("fma.rn.f32x2 %0, %1, %2, %3;" : "=l"(d) : "l"(a), "l"(b), "l"(c))
#define PACK_F32X2(out, lo, hi) \
    asm("mov.b64 %0, {%1, %2};" : "=l"(out) : "f"(lo), "f"(hi))
#define UNPACK_F32X2(lo, hi, in) \
    asm("mov.b64 {%0, %1}, %2;" : "=f"(lo), "=f"(hi) : "l"(in))

// =====================================================================
// Phase 1:  pre[t,b,j] = sum_d X[t,b,d] * Wi[j,d] + bh[j]
// GEMM  M = 65536, N = 256, K = 256 -> d_out. f32x2-packed microtile.
// (unchanged from Round 4/5: measured ~145 us)
// =====================================================================
#define P1_BM 64
#define P1_BK 32
#define P1_BMP 66   // EVEN padded stride -> 8B-aligned LDS.64 a-pairs
#define P1_BNP 257  // padded stride for Bs

__global__ __launch_bounds__(256, 2)
void pre_gemm(const float* __restrict__ X, const float* __restrict__ Wi,
              const float* __restrict__ bh, float* __restrict__ out)
{
    __shared__ __align__(16) float As[P1_BK * P1_BMP];   // As[k][m]
    __shared__ __align__(16) float Bs[P1_BK * P1_BNP];   // Bs[k][n]

    const int tid = threadIdx.x;
    const int tx = tid & 31;
    const int ty = tid >> 5;
    const int row0 = blockIdx.x * P1_BM;

    uint64_t acc2[4][8];
#pragma unroll
    for (int r = 0; r < 4; r++)
#pragma unroll
        for (int c = 0; c < 8; c++) acc2[r][c] = 0ull;

    for (int k0 = 0; k0 < DD; k0 += P1_BK) {
#pragma unroll
        for (int i = 0; i < 2; i++) {
            int lin = i * 256 + tid;
            int m  = lin >> 3;
            int kq = lin & 7;
            float4 v = *(const float4*)(X + (row0 + m) * DD + k0 + kq * 4);
            As[(kq * 4 + 0) * P1_BMP + m] = v.x;
            As[(kq * 4 + 1) * P1_BMP + m] = v.y;
            As[(kq * 4 + 2) * P1_BMP + m] = v.z;
            As[(kq * 4 + 3) * P1_BMP + m] = v.w;
        }
#pragma unroll
        for (int i = 0; i < 8; i++) {
            int lin = i * 256 + tid;
            int n  = lin >> 3;
            int kq = lin & 7;
            float4 v = *(const float4*)(Wi + n * DD + k0 + kq * 4);
            Bs[(kq * 4 + 0) * P1_BNP + n] = v.x;
            Bs[(kq * 4 + 1) * P1_BNP + n] = v.y;
            Bs[(kq * 4 + 2) * P1_BNP + n] = v.z;
            Bs[(kq * 4 + 3) * P1_BNP + n] = v.w;
        }
        __syncthreads();

#pragma unroll 8
        for (int k = 0; k < P1_BK; k++) {
            const uint64_t* ap = (const uint64_t*)(As + k * P1_BMP + ty * 8);
            uint64_t a2[4];
            a2[0] = ap[0]; a2[1] = ap[1]; a2[2] = ap[2]; a2[3] = ap[3];
#pragma unroll
            for (int c = 0; c < 8; c++) {
                float bv = Bs[k * P1_BNP + c * 32 + tx];
                uint64_t bb;
                PACK_F32X2(bb, bv, bv);
#pragma unroll
                for (int r = 0; r < 4; r++)
                    FMA_F32X2(acc2[r][c], a2[r], bb, acc2[r][c]);
            }
        }
        __syncthreads();
    }

    float bias[8];
#pragma unroll
    for (int c = 0; c < 8; c++) bias[c] = bh[c * 32 + tx];
#pragma unroll
    for (int r = 0; r < 4; r++) {
        float* orow0 = out + (row0 + ty * 8 + 2 * r + 0) * HH;
        float* orow1 = out + (row0 + ty * 8 + 2 * r + 1) * HH;
#pragma unroll
        for (int c = 0; c < 8; c++) {
            float lo, hi;
            UNPACK_F32X2(lo, hi, acc2[r][c]);
            orow0[c * 32 + tx] = lo + bias[c];
            orow1[c * 32 + tx] = hi + bias[c];
        }
    }
}

// =====================================================================
// Phase 2: sequential recurrence, WARP-LOCAL k-split (shfl combine).
// One CTA per batch row b (128 CTAs), 512 threads = 16 warps.
//   warp w (0..15), lane l (0..31):
//     j     = w*16 + (l & 15)        (output index; 16 outputs per warp)
//     kbase = (l >> 4) * 128         (k half owned by this lane)
//   Wh[j][kbase+0 .. kbase+95]  -> 24 float4 registers
//   Wh[j][kbase+96.. kbase+127] -> smem, interleaved for conflict-free
//                                  LDS.128 at (float4*)Wh_s + tid + c*512
//   h -> smem double buffer; per-warp reads hit 2 distinct 16B addrs.
// Combine: s_total = s + shfl_xor(s, 16)  -> NO smem partials, ONE
// __syncthreads per step (orders h_s write vs next step's reads).
// Scalar FFMA throughout.
// =====================================================================
#define P2_T    512
#define P2_KREG 96                      // per-thread k-values in registers
#define P2_KSM  32                      // per-thread k-values in smem
#define WHS_FLOATS (8 * 2048)           // 8 c-groups x 512 thr x 4 = 64KB
#define P2_SMEM_FLOATS (WHS_FLOATS + 2 * HH)
#define P2_SMEM_BYTES (P2_SMEM_FLOATS * (int)sizeof(float))

__global__ __launch_bounds__(P2_T, 1)
void rnn_seq(const float* __restrict__ Wh, const float* __restrict__ h0,
             float* __restrict__ out)
{
    extern __shared__ __align__(16) float sm[];
    float* Wh_s = sm;                       // 16384 floats
    float* h_s  = sm + WHS_FLOATS;          // 2 x 256

    const int tid  = threadIdx.x;
    const int l    = tid & 31;
    const int w    = tid >> 5;
    const int j    = w * 16 + (l & 15);     // output index
    const int kbase = (l >> 4) * 128;       // owned k half
    const bool lo_lane = (l < 16);
    const int b = blockIdx.x;

    // ---- register-resident weights: Wh[j][kbase .. kbase+95] ----
    float4 wr[P2_KREG / 4];
#pragma unroll
    for (int i = 0; i < P2_KREG / 4; i++)
        wr[i] = *(const float4*)(Wh + j * HH + kbase + i * 4);

    // ---- smem-resident weights (interleaved, conflict-free LDS.128) ----
    // Wh_s[(k>>2)*2048 + tt*4 + (k&3)] = Wh[j(tt)][kbase(tt)+96+k], k=0..31
    for (int idx = tid; idx < P2_T * P2_KSM; idx += P2_T) {
        int k  = idx & 31;
        int tt = idx >> 5;
        int jj = (tt >> 5) * 16 + (tt & 15);
        int kk = ((tt & 16) >> 4) * 128 + P2_KREG + k;
        Wh_s[(k >> 2) * 2048 + tt * 4 + (k & 3)] = Wh[jj * HH + kk];
    }
    if (tid < HH) h_s[tid] = h0[b * HH + tid];
    __syncthreads();

    const int base = b * HH + j;
    float pre = lo_lane ? out[base] : 0.0f;   // pre[0] (low lanes carry it)

    const float4* wsm = (const float4*)(Wh_s) + tid;  // + c*512 per group

    for (int t = 0; t < TT; t++) {
        float pre_next = 0.0f;
        if (lo_lane && t + 1 < TT)
            pre_next = out[(t + 1) * (BB * HH) + base];

        const float* hc = h_s + (t & 1) * HH + kbase;

        float a0 = pre, a1 = 0.0f, a2 = 0.0f, a3 = 0.0f;
        // k-offsets 0..95: register weights, h broadcast from smem
#pragma unroll
        for (int c = 0; c < P2_KREG / 4; c++) {
            float4 h4 = *(const float4*)(hc + c * 4);
            a0 += h4.x * wr[c].x;
            a1 += h4.y * wr[c].y;
            a2 += h4.z * wr[c].z;
            a3 += h4.w * wr[c].w;
        }
        // k-offsets 96..127: smem weights, conflict-free LDS.128
#pragma unroll
        for (int c = 0; c < P2_KSM / 4; c++) {
            float4 h4 = *(const float4*)(hc + P2_KREG + c * 4);
            float4 w4 = wsm[c * 512];
            a0 += h4.x * w4.x;
            a1 += h4.y * w4.y;
            a2 += h4.z * w4.z;
            a3 += h4.w * w4.w;
        }
        float s = (a0 + a1) + (a2 + a3);

        // combine k-halves within the warp: lane l <-> lane l^16
        s += __shfl_xor_sync(0xffffffffu, s, 16);

        float hn = __fdividef(1.0f, 1.0f + __expf(-s));
        if (lo_lane) {
            out[t * (BB * HH) + base] = hn;    // result
            h_s[((t + 1) & 1) * HH + j] = hn;  // next step's h
        }
        __syncthreads();                        // h_s ready for step t+1
        pre = pre_next;
    }
}

// =====================================================================
// Launch
// Inputs: X [T,B,D], h [B,H], Wi [H,D], Wh [H,H], bh [H], many_to_many.
// =====================================================================
extern "C" void kernel_launch(void* const* d_in, const int* in_sizes, int n_in,
                              void* d_out, int out_size)
{
    const float* X  = (const float*)d_in[0];
    const float* h0 = (const float*)d_in[1];
    const float* Wi = (const float*)d_in[2];
    const float* Wh = (const float*)d_in[3];
    const float* bh = (const float*)d_in[4];
    float* out = (float*)d_out;

    pre_gemm<<<(TT * BB) / P1_BM, 256>>>(X, Wi, bh, out);

    cudaFuncSetAttribute(rnn_seq, cudaFuncAttributeMaxDynamicSharedMemorySize,
                         P2_SMEM_BYTES);
    rnn_seq<<<BB, P2_T, P2_SMEM_BYTES>>>(Wh, h0, out);
}